// round 12
// baseline (speedup 1.0000x reference)
#include <cuda_runtime.h>
#include <cstdint>

// Problem constants (fixed: B_SZ=2, SEQ=4096, D=4096, R=8, U=4)
#define D_DIM  4096
#define D4     1024          // float4 per row
#define R_DIM  8
#define U_DIM  4
#define N_ROWS 8192

// Final t = scale * (B @ x^T): 8192 x 8 floats = 256 KB (static, allowed).
__device__ float g_t[N_ROWS * R_DIM];

// Packed f32x2 FMA: d = a*b + d
__device__ __forceinline__ void fma_f32x2(unsigned long long& d,
                                          unsigned long long a,
                                          unsigned long long b)
{
    asm("fma.rn.f32x2 %0, %1, %2, %0;" : "+l"(d) : "l"(a), "l"(b));
}

__device__ __forceinline__ uint32_t smem_u32(const void* p)
{
    uint32_t a;
    asm("{ .reg .u64 t; cvta.to.shared.u64 t, %1; cvt.u32.u64 %0, t; }"
        : "=r"(a) : "l"(p));
    return a;
}

__device__ __forceinline__ void mbar_wait_parity0(uint32_t mbar)
{
    asm volatile(
        "{\n\t"
        ".reg .pred P;\n\t"
        "W_%=:\n\t"
        "mbarrier.try_wait.parity.acquire.cta.shared::cta.b64 P, [%0], 0, 0x989680;\n\t"
        "@P bra.uni D_%=;\n\t"
        "bra.uni W_%=;\n\t"
        "D_%=:\n\t"
        "}"
        :: "r"(mbar) : "memory");
}

// ======================= Phase 1: t[n,r] = scale[r] * (B[r,:] . x[n,:]) =====
// TMA-staged: one cp.async.bulk copies this block's 2 contiguous x rows
// (32 KB) into smem — x never touches a per-thread load scoreboard (the
// mechanism every LDG variant R7-R11 was stuck on at ~3 TB/s). 4 blocks/SM
// keep 128 KB of bulk copies in flight; blocks pipeline each other.
// Warps split k 8-ways; FFMA2 accumulators (32 regs); full k per block so
// no split-k fold. B read via LDG (L1/L2-hot).
#define P1_THREADS 256
#define XS_ROWS 2            // rows per block (one 32 KB contiguous copy)
#define XS_BYTES (XS_ROWS * D_DIM * 4)

__global__ __launch_bounds__(P1_THREADS, 4)
void phase1_kernel(const float* __restrict__ x,
                   const float* __restrict__ B,
                   const float* __restrict__ P,
                   const float* __restrict__ v)
{
    __shared__ alignas(128) float xs[XS_ROWS][D_DIM];       // 32 KB
    __shared__ float s_part[8][XS_ROWS][R_DIM];              // 512 B
    __shared__ alignas(8) unsigned long long mbar;

    const int tid  = threadIdx.x;
    const int w    = tid >> 5;
    const int lane = tid & 31;
    const int row0 = blockIdx.x * XS_ROWS;

    const uint32_t mbar_a = smem_u32(&mbar);
    const uint32_t xs_a   = smem_u32(&xs[0][0]);

    if (tid == 0) {
        asm volatile("mbarrier.init.shared.b64 [%0], 1;" :: "r"(mbar_a) : "memory");
    }
    __syncthreads();

    if (tid == 0) {
        asm volatile("mbarrier.arrive.expect_tx.shared.b64 _, [%0], %1;"
                     :: "r"(mbar_a), "r"((uint32_t)XS_BYTES) : "memory");
        asm volatile(
            "cp.async.bulk.shared::cluster.global.mbarrier::complete_tx::bytes "
            "[%0], [%1], %2, [%3];"
            :: "r"(xs_a), "l"(x + (size_t)row0 * D_DIM),
               "r"((uint32_t)XS_BYTES), "r"(mbar_a)
            : "memory");
    }

    const ulonglong2* __restrict__ B2 = reinterpret_cast<const ulonglong2*>(B);

    // scale[r] = P[r,:] . v — compute while the bulk copy is in flight.
    float sc = 0.f;
    if (tid < R_DIM) {
        #pragma unroll
        for (int u = 0; u < U_DIM; u++) sc += P[tid * U_DIM + u] * v[u];
    }

    mbar_wait_parity0(mbar_a);

    // Warp w owns k-f4 slice [w*128, w*128+128); lanes take 4 iters of 32.
    unsigned long long acc2[XS_ROWS][R_DIM];   // f32x2 accumulators, 32 regs
    #pragma unroll
    for (int a = 0; a < XS_ROWS; a++)
        #pragma unroll
        for (int r = 0; r < R_DIM; r++) acc2[a][r] = 0ull;

    const ulonglong2* __restrict__ xs0 = reinterpret_cast<const ulonglong2*>(xs[0]);
    const ulonglong2* __restrict__ xs1 = reinterpret_cast<const ulonglong2*>(xs[1]);

    #pragma unroll
    for (int i = 0; i < 4; i++) {
        const int kf4 = w * 128 + i * 32 + lane;
        const ulonglong2 xv0 = xs0[kf4];       // LDS.128, conflict-free
        const ulonglong2 xv1 = xs1[kf4];
        #pragma unroll
        for (int r = 0; r < R_DIM; r++) {
            const ulonglong2 bv = B2[r * D4 + kf4];   // L1/L2-hot
            fma_f32x2(acc2[0][r], xv0.x, bv.x);
            fma_f32x2(acc2[0][r], xv0.y, bv.y);
            fma_f32x2(acc2[1][r], xv1.x, bv.x);
            fma_f32x2(acc2[1][r], xv1.y, bv.y);
        }
    }

    // Unpack + butterfly-reduce across lanes.
    float acc[XS_ROWS][R_DIM];
    #pragma unroll
    for (int a = 0; a < XS_ROWS; a++)
        #pragma unroll
        for (int r = 0; r < R_DIM; r++) {
            float lo, hi;
            asm("mov.b64 {%0, %1}, %2;" : "=f"(lo), "=f"(hi) : "l"(acc2[a][r]));
            acc[a][r] = lo + hi;
        }
    #pragma unroll
    for (int a = 0; a < XS_ROWS; a++)
        #pragma unroll
        for (int r = 0; r < R_DIM; r++)
            #pragma unroll
            for (int off = 16; off > 0; off >>= 1)
                acc[a][r] += __shfl_xor_sync(0xFFFFFFFFu, acc[a][r], off);

    if (lane == 0) {
        #pragma unroll
        for (int a = 0; a < XS_ROWS; a++)
            #pragma unroll
            for (int r = 0; r < R_DIM; r++) s_part[w][a][r] = acc[a][r];
    }
    // stash scale for the finalize threads
    __shared__ float s_scale[R_DIM];
    if (tid < R_DIM) s_scale[tid] = sc;
    __syncthreads();

    // Finalize: 16 threads, one (row, r) each; cross-warp sum + scale.
    if (tid < XS_ROWS * R_DIM) {
        const int m = tid >> 3, r = tid & 7;
        float s = 0.f;
        #pragma unroll
        for (int ww = 0; ww < 8; ww++) s += s_part[ww][m][r];
        g_t[(size_t)(row0 + m) * R_DIM + r] = s * s_scale[r];
    }
}

// ======================= Phase 2: out[n,d] = base[n,d] + sum_r t[n,r]*A[d,r] =
// R10 measured-best form (46.9 us), minus the split-k fold: t is final.
#define P2_THREADS 256
#define NT2 32                // rows per block
#define DT4 256               // float4 columns per block

__global__ __launch_bounds__(P2_THREADS)
void phase2_kernel(const float* __restrict__ base,
                   const float* __restrict__ A,
                   float* __restrict__ out)
{
    __shared__ float ts[NT2][R_DIM];          // 1 KB

    const int tid  = threadIdx.x;
    const int row0 = blockIdx.x * NT2;
    const int d4   = blockIdx.y * DT4 + tid;

    const float4* __restrict__ A4    = reinterpret_cast<const float4*>(A);
    const float4* __restrict__ base4 = reinterpret_cast<const float4*>(base);
    float4* __restrict__ out4        = reinterpret_cast<float4*>(out);

    // t tile: NT2*8 = 256 floats, one per thread (already scaled).
    ts[tid >> 3][tid & 7] = g_t[(size_t)(row0 + (tid >> 3)) * R_DIM + (tid & 7)];

    // A rows for this thread's 4 consecutive d's.
    float4 a[8];
    #pragma unroll
    for (int j = 0; j < 8; j++)
        a[j] = A4[(size_t)d4 * 8 + j];

    __syncthreads();

    // prologue: load chunk 0
    float4 bv[4];
    #pragma unroll
    for (int i = 0; i < 4; i++)
        bv[i] = __ldcs(&base4[(size_t)(row0 + i) * D4 + d4]);

    #pragma unroll 1
    for (int c = 0; c < NT2; c += 4) {
        float4 nv[4];
        if (c + 4 < NT2) {
            #pragma unroll
            for (int i = 0; i < 4; i++)
                nv[i] = __ldcs(&base4[(size_t)(row0 + c + 4 + i) * D4 + d4]);
        }

        #pragma unroll
        for (int i = 0; i < 4; i++) {
            const int mm = c + i;
            const float t0 = ts[mm][0], t1 = ts[mm][1], t2 = ts[mm][2], t3 = ts[mm][3];
            const float t4 = ts[mm][4], t5 = ts[mm][5], t6 = ts[mm][6], t7 = ts[mm][7];
            float4 o;
            o.x = bv[i].x + t0*a[0].x + t1*a[0].y + t2*a[0].z + t3*a[0].w
                          + t4*a[1].x + t5*a[1].y + t6*a[1].z + t7*a[1].w;
            o.y = bv[i].y + t0*a[2].x + t1*a[2].y + t2*a[2].z + t3*a[2].w
                          + t4*a[3].x + t5*a[3].y + t6*a[3].z + t7*a[3].w;
            o.z = bv[i].z + t0*a[4].x + t1*a[4].y + t2*a[4].z + t3*a[4].w
                          + t4*a[5].x + t5*a[5].y + t6*a[5].z + t7*a[5].w;
            o.w = bv[i].w + t0*a[6].x + t1*a[6].y + t2*a[6].z + t3*a[6].w
                          + t4*a[7].x + t5*a[7].y + t6*a[7].z + t7*a[7].w;
            __stcs(&out4[(size_t)(row0 + mm) * D4 + d4], o);
        }
        #pragma unroll
        for (int i = 0; i < 4; i++) bv[i] = nv[i];
    }
}

extern "C" void kernel_launch(void* const* d_in, const int* in_sizes, int n_in,
                              void* d_out, int out_size)
{
    const float* x    = (const float*)d_in[0];
    const float* base = (const float*)d_in[1];
    const float* A    = (const float*)d_in[2];
    const float* B    = (const float*)d_in[3];
    const float* P    = (const float*)d_in[4];
    const float* v    = (const float*)d_in[5];
    float* out = (float*)d_out;

    phase1_kernel<<<N_ROWS / XS_ROWS, P1_THREADS>>>(x, B, P, v);  // 4096 blocks

    dim3 g2(N_ROWS / NT2, D_DIM / (DT4 * 4));     // (256, 4) = 1024 blocks
    phase2_kernel<<<g2, P2_THREADS>>>(base, A, out);
}